// round 6
// baseline (speedup 1.0000x reference)
#include <cuda_runtime.h>
#include <cstdint>

#define T_LEN 131072
#define HALF_T (T_LEN / 2)
#define D_X 16
#define D_L 8

// d_out layout (flat concat of reference tuple, all float32)
#define OFF_RECON 0
#define OFF_PRED  (T_LEN * D_X)
#define OFF_LMP   (2 * T_LEN * D_X)
#define OFF_LVP   (OFF_LMP + 2 * T_LEN * D_L)
#define OFF_CT    (OFF_LVP + 2 * T_LEN * D_L)
#define OFF_CT1   (OFF_CT + T_LEN * D_X * D_L)

// ---------------------------------------------------------------------------
// Packed fp32x2 ops (Blackwell)
// ---------------------------------------------------------------------------
__device__ __forceinline__ float2 ffma2(float2 a, float2 b, float2 c) {
    float2 d;
    asm("{\n\t"
        ".reg .b64 ra, rb, rc, rd;\n\t"
        "mov.b64 ra, {%2, %3};\n\t"
        "mov.b64 rb, {%4, %5};\n\t"
        "mov.b64 rc, {%6, %7};\n\t"
        "fma.rn.f32x2 rd, ra, rb, rc;\n\t"
        "mov.b64 {%0, %1}, rd;\n\t"
        "}"
        : "=f"(d.x), "=f"(d.y)
        : "f"(a.x), "f"(a.y), "f"(b.x), "f"(b.y), "f"(c.x), "f"(c.y));
    return d;
}
__device__ __forceinline__ float2 fmul2(float2 a, float2 b) {
    float2 d;
    asm("{\n\t"
        ".reg .b64 ra, rb, rd;\n\t"
        "mov.b64 ra, {%2, %3};\n\t"
        "mov.b64 rb, {%4, %5};\n\t"
        "mul.rn.f32x2 rd, ra, rb;\n\t"
        "mov.b64 {%0, %1}, rd;\n\t"
        "}"
        : "=f"(d.x), "=f"(d.y)
        : "f"(a.x), "f"(a.y), "f"(b.x), "f"(b.y));
    return d;
}

// ---------------------------------------------------------------------------
// Preprocessed decoder weights (device-global scratch; no allocation).
// ---------------------------------------------------------------------------
__device__ __align__(16) float g_w0t[D_X * 64 * 32];  // [n][j][f]
__device__ __align__(16) float g_w12[D_X * 64];       // collapsed lw1@lw2
__device__ __align__(16) float g_beff[D_X];           // lb1@lw2 + lb2

__global__ void prep_kernel(const float* __restrict__ lw0,
                            const float* __restrict__ lw1,
                            const float* __restrict__ lw2,
                            const float* __restrict__ lb0,
                            const float* __restrict__ lb1,
                            const float* __restrict__ lb2,
                            float* __restrict__ out) {
    int tid = threadIdx.x;          // 1024 threads: (n, j)
    int n = tid >> 6;
    int j = tid & 63;
#pragma unroll
    for (int f = 0; f < 32; f++)
        g_w0t[(n * 64 + j) * 32 + f] = lw0[(n * 32 + f) * 64 + j];
    float acc = 0.f;
#pragma unroll 8
    for (int o = 0; o < 64; o++)
        acc = fmaf(lw1[(n * 64 + j) * 64 + o], lw2[n * 64 + o], acc);
    g_w12[n * 64 + j] = acc;
    if (j == 0) {
        float b = lb2[n];
        for (int o = 0; o < 64; o++)
            b = fmaf(lb1[n * 64 + o], lw2[n * 64 + o], b);
        g_beff[n] = b;
    }
    __syncthreads();
    // pred[0]: features are all-zero -> h = relu(lb0), out = relu(h.w12 + beff)
    if (j == 0) {
        float s = g_beff[n];
        for (int o = 0; o < 64; o++) {
            float h = fmaxf(lb0[n * 64 + o], 0.f);
            s = fmaf(h, g_w12[n * 64 + o], s);
        }
        out[OFF_PRED + n] = fmaxf(s, 0.f);
    }
}

// ---------------------------------------------------------------------------
// enc layers 0+1 (packed block: w0[8] b0[8] w1[64] b1[8]) -> h1[8]
// ---------------------------------------------------------------------------
__device__ __forceinline__ void enc01(float s, const float* __restrict__ w,
                                      float* __restrict__ h1) {
    float h0[8];
#pragma unroll
    for (int i = 0; i < 8; i++) {
        float v = fmaf(s, w[i], w[8 + i]);
        h0[i] = v > 0.f ? v : 0.01f * v;
    }
#pragma unroll
    for (int j = 0; j < 8; j++) {
        float a = 0.f;
#pragma unroll
        for (int i = 0; i < 8; i++) a = fmaf(h0[i], w[16 + i * 8 + j], a);
        a += w[80 + j];
        h1[j] = a > 0.f ? a : 0.01f * a;
    }
}

__device__ __forceinline__ float dot8(const float* __restrict__ h,
                                      float4 a, float4 b, float bias) {
    float c = bias;
    c = fmaf(h[0], a.x, c); c = fmaf(h[1], a.y, c);
    c = fmaf(h[2], a.z, c); c = fmaf(h[3], a.w, c);
    c = fmaf(h[4], b.x, c); c = fmaf(h[5], b.y, c);
    c = fmaf(h[6], b.z, c); c = fmaf(h[7], b.w, c);
    return c;
}

// dot of two 8-vectors given as float4 pairs (register-safe, no pointer tricks)
__device__ __forceinline__ float dot8v(float4 x0, float4 x1,
                                       float4 w0, float4 w1, float bias) {
    float c = bias;
    c = fmaf(x0.x, w0.x, c); c = fmaf(x0.y, w0.y, c);
    c = fmaf(x0.z, w0.z, c); c = fmaf(x0.w, w0.w, c);
    c = fmaf(x1.x, w1.x, c); c = fmaf(x1.y, w1.y, c);
    c = fmaf(x1.z, w1.z, c); c = fmaf(x1.w, w1.w, c);
    return c;
}

// ---------------------------------------------------------------------------
// Paired head: two rows sharing every weight load.
// ---------------------------------------------------------------------------
__device__ __forceinline__ void head_fn2(const float* __restrict__ xa8,
                                         const float* __restrict__ xb8,
                                         const float* __restrict__ w1t,
                                         const float* __restrict__ b1,
                                         const float* __restrict__ w2,
                                         const float* __restrict__ b2,
                                         float* __restrict__ dsta,
                                         float* __restrict__ dstb) {
    float4 xa0 = *(const float4*)&xa8[0];
    float4 xa1 = *(const float4*)&xa8[4];
    float4 xb0 = *(const float4*)&xb8[0];
    float4 xb1 = *(const float4*)&xb8[4];
    float4 b2a = *(const float4*)&b2[0];
    float4 b2b = *(const float4*)&b2[4];
    float2 oa0 = make_float2(b2a.x, b2a.y), oa1 = make_float2(b2a.z, b2a.w);
    float2 oa2 = make_float2(b2b.x, b2b.y), oa3 = make_float2(b2b.z, b2b.w);
    float2 ob0 = oa0, ob1 = oa1, ob2 = oa2, ob3 = oa3;
#pragma unroll 4
    for (int j = 0; j < 128; j++) {
        float4 wA = *(const float4*)&w1t[j * 8];
        float4 wB = *(const float4*)&w1t[j * 8 + 4];
        float ha = dot8v(xa0, xa1, wA, wB, b1[j]);
        float hb = dot8v(xb0, xb1, wA, wB, b1[j]);
        ha = fmaxf(ha, 0.f);
        hb = fmaxf(hb, 0.f);
        float2 hha = make_float2(ha, ha);
        float2 hhb = make_float2(hb, hb);
        float4 u = *(const float4*)&w2[j * 8];
        float4 v = *(const float4*)&w2[j * 8 + 4];
        float2 u0 = make_float2(u.x, u.y), u1 = make_float2(u.z, u.w);
        float2 v0 = make_float2(v.x, v.y), v1 = make_float2(v.z, v.w);
        oa0 = ffma2(hha, u0, oa0); oa1 = ffma2(hha, u1, oa1);
        oa2 = ffma2(hha, v0, oa2); oa3 = ffma2(hha, v1, oa3);
        ob0 = ffma2(hhb, u0, ob0); ob1 = ffma2(hhb, u1, ob1);
        ob2 = ffma2(hhb, v0, ob2); ob3 = ffma2(hhb, v1, ob3);
    }
    *(float4*)&dsta[0] = make_float4(oa0.x, oa0.y, oa1.x, oa1.y);
    *(float4*)&dsta[4] = make_float4(oa2.x, oa2.y, oa3.x, oa3.y);
    *(float4*)&dstb[0] = make_float4(ob0.x, ob0.y, ob1.x, ob1.y);
    *(float4*)&dstb[4] = make_float4(ob2.x, ob2.y, ob3.x, ob3.y);
}

// ---------------------------------------------------------------------------
// Mega kernel: thread handles TWO timesteps (t0, t1 = t0 + T/2) so every
// decoder weight load feeds 8 FFMA2 (R,P x t0,t1). blockIdx.y = quarter
// (nodes 4q..4q+3; head-row pair q).
// ---------------------------------------------------------------------------
#define BS 352
#define GX ((HALF_T + BS - 1) / BS)   // 187

// smem float offsets
#define S_W0    0                    // 4*64*32 = 8192
#define S_BW    8192                 // [ln][j] (b0, w12) pairs: 512
#define S_BEFF  8704                 // 4
#define S_CL01  8708                 // 88
#define S_PL01  8796                 // 88
#define S_CW2T  8884                 // [ln][k][i] 256
#define S_CB2   9140                 // 32
#define S_PW2T  9172                 // 256
#define S_PB2   9428                 // 32
#define S_HW1T  9460                 // 1024
#define S_HB1   10484                // 128
#define S_HW2   10612                // 1024
#define S_HB2   11636                // 8
#define S_TOT   11644
#define MEGA_SMEM_BYTES (S_TOT * 4)  // ~46.6 KB

// Build features for one timestep of one node: fR = gate ? [M,V] : 0,
// fP = cp * [M,V].  Slots: [k]=mean-pair, [8+k]=logvar-pair.
__device__ __forceinline__ void build_feats(
    const float* __restrict__ lm, const float* __restrict__ lv,
    const float* __restrict__ smem, int ln, size_t t,
    unsigned byteM, const float* __restrict__ h1p,
    float2* __restrict__ fR, float2* __restrict__ fP) {
    const float4* lm4 = (const float4*)lm;
    const float4* lv4 = (const float4*)lv;
    const float2 zz = make_float2(0.f, 0.f);
#pragma unroll
    for (int c = 0; c < 2; c++) {
        float4 ma = lm4[t * 2 + c];
        float4 mb = lm4[((size_t)T_LEN + t) * 2 + c];
        float4 va = lv4[t * 2 + c];
        float4 vb = lv4[((size_t)T_LEN + t) * 2 + c];
        const float* maf = (const float*)&ma;
        const float* mbf = (const float*)&mb;
        const float* vaf = (const float*)&va;
        const float* vbf = (const float*)&vb;
#pragma unroll
        for (int kk = 0; kk < 4; kk++) {
            int k = c * 4 + kk;
            const float4* w4p = (const float4*)(smem + S_PW2T + (ln * 8 + k) * 8);
            float cp = dot8(h1p, w4p[0], w4p[1], smem[S_PB2 + ln * 8 + k]);
            float2 cp2 = make_float2(cp, cp);
            float2 Mk = make_float2(maf[kk], mbf[kk]);
            float2 Vk = make_float2(vaf[kk], vbf[kk]);
            bool on = (byteM >> k) & 1u;
            fR[k]     = on ? Mk : zz;
            fR[8 + k] = on ? Vk : zz;
            fP[k]     = fmul2(cp2, Mk);
            fP[8 + k] = fmul2(cp2, Vk);
        }
    }
}

__global__ __launch_bounds__(BS, 1)
void mega_kernel(const float* __restrict__ lm, const float* __restrict__ lv,
                 const float* __restrict__ Tin,
                 const float* cw0, const float* cb0, const float* cw1,
                 const float* cb1, const float* cw2, const float* cb2,
                 const float* pw0, const float* pb0, const float* pw1,
                 const float* pb1, const float* pw2, const float* pb2,
                 const float* fmw1, const float* fmb1,
                 const float* fmw2, const float* fmb2,
                 const float* fvw1, const float* fvb1,
                 const float* fvw2, const float* fvb2,
                 const float* __restrict__ lb0,
                 float* __restrict__ out) {
    extern __shared__ __align__(16) float smem[];
    const int tid = threadIdx.x;
    const int q = blockIdx.y;
    const int nb = q * 4;             // node base

    // ---- cooperative smem fill ----
    for (int i = tid; i < (4 * 64 * 32) / 4; i += BS)
        ((float4*)(smem + S_W0))[i] = ((const float4*)(g_w0t + nb * 2048))[i];
    for (int i = tid; i < 256; i += BS) {
        smem[S_BW + 2 * i]     = lb0[nb * 64 + i];
        smem[S_BW + 2 * i + 1] = g_w12[nb * 64 + i];
    }
    if (tid < 4) smem[S_BEFF + tid] = g_beff[nb + tid];
    for (int i = tid; i < 88; i += BS) {
        float v, u;
        if (i < 8)       { v = cw0[i];      u = pw0[i];      }
        else if (i < 16) { v = cb0[i - 8];  u = pb0[i - 8];  }
        else if (i < 80) { v = cw1[i - 16]; u = pw1[i - 16]; }
        else             { v = cb1[i - 80]; u = pb1[i - 80]; }
        smem[S_CL01 + i] = v;
        smem[S_PL01 + i] = u;
    }
    for (int i = tid; i < 256; i += BS) {
        int ln = i >> 6, k = (i >> 3) & 7, ii = i & 7;
        int src = ii * 128 + (nb + ln) * 8 + k;
        smem[S_CW2T + i] = cw2[src];
        smem[S_PW2T + i] = pw2[src];
    }
    for (int i = tid; i < 32; i += BS) {
        smem[S_CB2 + i] = cb2[nb * 8 + i];
        smem[S_PB2 + i] = pb2[nb * 8 + i];
    }
    {
        const float* hw1 = (q >> 1) ? fvw1 : fmw1;
        const float* hw2 = (q >> 1) ? fvw2 : fmw2;
        const float* hb1 = (q >> 1) ? fvb1 : fmb1;
        const float* hb2 = (q >> 1) ? fvb2 : fmb2;
        for (int i = tid; i < 1024; i += BS) {
            int j = i >> 3, k = i & 7;
            smem[S_HW1T + i] = hw1[k * 128 + j];
            smem[S_HW2 + i]  = hw2[i];
        }
        if (tid < 128) smem[S_HB1 + tid] = hb1[tid];
        if (tid < 8)   smem[S_HB2 + tid] = hb2[tid];
    }
    __syncthreads();

    const int tb = blockIdx.x * BS + tid;
    if (tb >= HALF_T) return;
    const size_t t0 = (size_t)tb;
    const size_t t1 = (size_t)tb + HALF_T;

    // ---- enc phase for both timesteps ----
    unsigned mask0 = 0, mask1 = 0;    // 4 node-bytes each
    {
        float sA = Tin[t0];
        float sB = Tin[t1];
        // binarized Ct (quarter's 32 cols) for t0 and t1
        float h1a[8], h1b[8];
        enc01(sA, smem + S_CL01, h1a);
        enc01(sB, smem + S_CL01, h1b);
        float* dA = out + OFF_CT + t0 * 128 + nb * 8;
        float* dB = out + OFF_CT + t1 * 128 + nb * 8;
#pragma unroll
        for (int ln = 0; ln < 4; ln++) {
            float va[8], vb[8];
#pragma unroll
            for (int k = 0; k < 8; k++) {
                const float4* w4 = (const float4*)(smem + S_CW2T + (ln * 8 + k) * 8);
                float4 wa = w4[0], wb = w4[1];
                float bia = smem[S_CB2 + ln * 8 + k];
                float aA = dot8(h1a, wa, wb, bia);
                float aB = dot8(h1b, wa, wb, bia);
                bool onA = !(aA < 0.1f);
                bool onB = !(aB < 0.1f);
                va[k] = onA ? 1.f : 0.f;
                vb[k] = onB ? 1.f : 0.f;
                if (onA) mask0 |= 1u << (ln * 8 + k);
                if (onB) mask1 |= 1u << (ln * 8 + k);
            }
            *(float4*)&dA[ln * 8]     = make_float4(va[0], va[1], va[2], va[3]);
            *(float4*)&dA[ln * 8 + 4] = make_float4(va[4], va[5], va[6], va[7]);
            *(float4*)&dB[ln * 8]     = make_float4(vb[0], vb[1], vb[2], vb[3]);
            *(float4*)&dB[ln * 8 + 4] = make_float4(vb[4], vb[5], vb[6], vb[7]);
        }
        // continuous Ct_1 for t0 and t1
        enc01(sA, smem + S_PL01, h1a);
        enc01(sB, smem + S_PL01, h1b);
        dA = out + OFF_CT1 + t0 * 128 + nb * 8;
        dB = out + OFF_CT1 + t1 * 128 + nb * 8;
#pragma unroll
        for (int ln = 0; ln < 4; ln++) {
            float va[8], vb[8];
#pragma unroll
            for (int k = 0; k < 8; k++) {
                const float4* w4 = (const float4*)(smem + S_PW2T + (ln * 8 + k) * 8);
                float4 wa = w4[0], wb = w4[1];
                float bia = smem[S_PB2 + ln * 8 + k];
                va[k] = dot8(h1a, wa, wb, bia);
                vb[k] = dot8(h1b, wa, wb, bia);
            }
            *(float4*)&dA[ln * 8]     = make_float4(va[0], va[1], va[2], va[3]);
            *(float4*)&dA[ln * 8 + 4] = make_float4(va[4], va[5], va[6], va[7]);
            *(float4*)&dB[ln * 8]     = make_float4(vb[0], vb[1], vb[2], vb[3]);
            *(float4*)&dB[ln * 8 + 4] = make_float4(vb[4], vb[5], vb[6], vb[7]);
        }
    }
    const bool hasP1 = (t1 + 1 < T_LEN);
    float h1p0[8], h1p1[8];
    enc01(Tin[t0 + 1], smem + S_PL01, h1p0);
    {
        float s2 = hasP1 ? Tin[t1 + 1] : 0.f;
        enc01(s2, smem + S_PL01, h1p1);
    }

    // ---- head phase: quarter q handles row pair (rb+t0, rb+t1) ----
    {
        const float* x = (q >> 1) ? lv : lm;
        float* hdst = out + ((q >> 1) ? OFF_LVP : OFF_LMP);
        size_t rb = (q & 1) ? (size_t)T_LEN : 0;
        head_fn2(x + (rb + t0) * 8, x + (rb + t1) * 8,
                 smem + S_HW1T, smem + S_HB1, smem + S_HW2, smem + S_HB2,
                 hdst + (rb + t0) * 8, hdst + (rb + t1) * 8);
    }

    // ---- decode: per node, build features for both t's, one j-loop ----
    const float2 zz = make_float2(0.f, 0.f);

    for (int ln = 0; ln < 4; ln++) {
        float2 fR0[16], fP0[16], fR1[16], fP1[16];
        build_feats(lm, lv, smem, ln, t0, (mask0 >> (ln * 8)) & 0xffu, h1p0,
                    fR0, fP0);
        build_feats(lm, lv, smem, ln, t1, (mask1 >> (ln * 8)) & 0xffu, h1p1,
                    fR1, fP1);

        float outR0 = 0.f, outP0 = 0.f, outR1 = 0.f, outP1 = 0.f;
        const float4* w4base = (const float4*)(smem + S_W0 + ln * 2048);
        const float2* bw = (const float2*)(smem + S_BW + 2 * ln * 64);
#pragma unroll 2
        for (int j = 0; j < 64; j++) {
            const float4* w4 = w4base + j * 8;
            float2 aR0 = zz, aP0 = zz, aR1 = zz, aP1 = zz;
#pragma unroll
            for (int qq = 0; qq < 8; qq++) {
                float4 wA = w4[qq];
                float2 w0p = make_float2(wA.x, wA.y);
                float2 w1p = make_float2(wA.z, wA.w);
                aR0 = ffma2(fR0[2 * qq],     w0p, aR0);
                aR0 = ffma2(fR0[2 * qq + 1], w1p, aR0);
                aP0 = ffma2(fP0[2 * qq],     w0p, aP0);
                aP0 = ffma2(fP0[2 * qq + 1], w1p, aP0);
                aR1 = ffma2(fR1[2 * qq],     w0p, aR1);
                aR1 = ffma2(fR1[2 * qq + 1], w1p, aR1);
                aP1 = ffma2(fP1[2 * qq],     w0p, aP1);
                aP1 = ffma2(fP1[2 * qq + 1], w1p, aP1);
            }
            float2 bwj = bw[j];
            float hR0 = fmaxf(aR0.x + aR0.y + bwj.x, 0.f);
            float hP0 = fmaxf(aP0.x + aP0.y + bwj.x, 0.f);
            float hR1 = fmaxf(aR1.x + aR1.y + bwj.x, 0.f);
            float hP1 = fmaxf(aP1.x + aP1.y + bwj.x, 0.f);
            outR0 = fmaf(hR0, bwj.y, outR0);
            outP0 = fmaf(hP0, bwj.y, outP0);
            outR1 = fmaf(hR1, bwj.y, outR1);
            outP1 = fmaf(hP1, bwj.y, outP1);
        }
        float be = smem[S_BEFF + ln];
        out[OFF_RECON + t0 * 16 + nb + ln] = fmaxf(outR0 + be, 0.f);
        out[OFF_RECON + t1 * 16 + nb + ln] = fmaxf(outR1 + be, 0.f);
        out[OFF_PRED + (t0 + 1) * 16 + nb + ln] = fmaxf(outP0 + be, 0.f);
        if (hasP1)
            out[OFF_PRED + (t1 + 1) * 16 + nb + ln] = fmaxf(outP1 + be, 0.f);
    }
}

// ---------------------------------------------------------------------------
extern "C" void kernel_launch(void* const* d_in, const int* in_sizes, int n_in,
                              void* d_out, int out_size) {
    const float* lm  = (const float*)d_in[0];
    const float* lv  = (const float*)d_in[1];
    const float* Tin = (const float*)d_in[2];
    const float* cw0 = (const float*)d_in[3];
    const float* cb0 = (const float*)d_in[4];
    const float* cw1 = (const float*)d_in[5];
    const float* cb1 = (const float*)d_in[6];
    const float* cw2 = (const float*)d_in[7];
    const float* cb2 = (const float*)d_in[8];
    const float* pw0 = (const float*)d_in[9];
    const float* pb0 = (const float*)d_in[10];
    const float* pw1 = (const float*)d_in[11];
    const float* pb1 = (const float*)d_in[12];
    const float* pw2 = (const float*)d_in[13];
    const float* pb2 = (const float*)d_in[14];
    const float* fmw1 = (const float*)d_in[15];
    const float* fmb1 = (const float*)d_in[16];
    const float* fmw2 = (const float*)d_in[17];
    const float* fmb2 = (const float*)d_in[18];
    const float* fvw1 = (const float*)d_in[19];
    const float* fvb1 = (const float*)d_in[20];
    const float* fvw2 = (const float*)d_in[21];
    const float* fvb2 = (const float*)d_in[22];
    const float* lw0 = (const float*)d_in[23];
    const float* lb0 = (const float*)d_in[24];
    const float* lw1 = (const float*)d_in[25];
    const float* lb1 = (const float*)d_in[26];
    const float* lw2 = (const float*)d_in[27];
    const float* lb2 = (const float*)d_in[28];
    float* out = (float*)d_out;

    cudaFuncSetAttribute(mega_kernel, cudaFuncAttributeMaxDynamicSharedMemorySize,
                         MEGA_SMEM_BYTES);

    prep_kernel<<<1, 1024>>>(lw0, lw1, lw2, lb0, lb1, lb2, out);
    dim3 grid(GX, 4);
    mega_kernel<<<grid, BS, MEGA_SMEM_BYTES>>>(
        lm, lv, Tin,
        cw0, cb0, cw1, cb1, cw2, cb2,
        pw0, pb0, pw1, pb1, pw2, pb2,
        fmw1, fmb1, fmw2, fmb2,
        fvw1, fvb1, fvw2, fvb2,
        lb0, out);
}